// round 16
// baseline (speedup 1.0000x reference)
#include <cuda_runtime.h>
#include <cuda_fp16.h>
#include <cstdint>

// Problem dims
#define T_TOK 4096
#define D_DIM 1024
#define E_EXP 8
#define H_DIM 4096

// ---------------- device scratch (no allocations allowed) ----------------
__device__ int    g_expert[T_TOK];
__device__ int    g_counts[E_EXP];
__device__ int    g_offsets[E_EXP + 1];
__device__ int    g_cursor[E_EXP];
__device__ int    g_perm[T_TOK];
__device__ float  g_probs[T_TOK * E_EXP];
__device__ __half g_hidden[(size_t)T_TOK * H_DIM];            // 32 MB
__device__ int    g_map[48];    // tile list: (e<<8)|mt, M-tile=128
__device__ int    g_ntile;

// ---------------- helpers ----------------
__device__ __forceinline__ float gelu_exact(float v) {
    return 0.5f * v * (1.0f + erff(v * 0.70710678118654752440f));
}
__device__ __forceinline__ uint32_t smem_u32(const void* p) {
    uint32_t a;
    asm("{ .reg .u64 t; cvta.to.shared.u64 t, %1; cvt.u32.u64 %0, t; }" : "=r"(a) : "l"(p));
    return a;
}
__device__ __forceinline__ uint32_t packh2(float a, float b) {
    __half2 h = __floats2half2_rn(a, b);
    return *reinterpret_cast<uint32_t*>(&h);
}
__device__ __forceinline__ void mma_f16(float* c, const uint32_t* a, const uint32_t* b) {
    asm volatile(
        "mma.sync.aligned.m16n8k16.row.col.f32.f16.f16.f32 "
        "{%0,%1,%2,%3}, {%4,%5,%6,%7}, {%8,%9}, {%0,%1,%2,%3};"
        : "+f"(c[0]), "+f"(c[1]), "+f"(c[2]), "+f"(c[3])
        : "r"(a[0]), "r"(a[1]), "r"(a[2]), "r"(a[3]), "r"(b[0]), "r"(b[1]));
}
__device__ __forceinline__ void cp_async16(uint32_t saddr, const void* gptr) {
    asm volatile("cp.async.cg.shared.global [%0], [%1], 16;" :: "r"(saddr), "l"(gptr));
}
__device__ __forceinline__ void cp_commit() {
    asm volatile("cp.async.commit_group;" ::: "memory");
}
template <int N>
__device__ __forceinline__ void cp_wait() {
    asm volatile("cp.async.wait_group %0;" :: "n"(N) : "memory");
}
// A-tile swizzled byte offset: row m (64B rows), half-pair word wk in 0..15
__device__ __forceinline__ uint32_t awb(int m, int wk) {
    return (uint32_t)(m * 64 + (((wk >> 2) ^ ((m >> 1) & 3)) << 4) + (wk & 3) * 4);
}

// ---------------- kernel 0: zero counters ----------------
__global__ void init_kernel() {
    if (threadIdx.x < E_EXP) g_counts[threadIdx.x] = 0;
}

// ---------------- kernel 1: router (one warp per token) ----------------
__global__ void router_kernel(const float* __restrict__ x,
                              const float* __restrict__ gum,
                              const float* __restrict__ rw,
                              const float* __restrict__ rb) {
    int gwarp = (blockIdx.x * blockDim.x + threadIdx.x) >> 5;
    int lane  = threadIdx.x & 31;
    if (gwarp >= T_TOK) return;

    const float* xr = x + (size_t)gwarp * D_DIM;
    float acc[8] = {0.f,0.f,0.f,0.f,0.f,0.f,0.f,0.f};
    for (int d = lane; d < D_DIM; d += 32) {
        float xv = xr[d];
        float4 wa = *reinterpret_cast<const float4*>(rw + (size_t)d * 8);
        float4 wb = *reinterpret_cast<const float4*>(rw + (size_t)d * 8 + 4);
        acc[0] += xv * wa.x; acc[1] += xv * wa.y; acc[2] += xv * wa.z; acc[3] += xv * wa.w;
        acc[4] += xv * wb.x; acc[5] += xv * wb.y; acc[6] += xv * wb.z; acc[7] += xv * wb.w;
    }
    #pragma unroll
    for (int o = 16; o > 0; o >>= 1)
        #pragma unroll
        for (int e = 0; e < 8; e++)
            acc[e] += __shfl_xor_sync(0xffffffffu, acc[e], o);

    if (lane == 0) {
        float lg[8];
        #pragma unroll
        for (int e = 0; e < 8; e++) lg[e] = acc[e] + rb[e];
        float zmax = -1e30f; int eid = 0; float lmax = -1e30f;
        #pragma unroll
        for (int e = 0; e < 8; e++) {
            float z = lg[e] + gum[(size_t)gwarp * 8 + e];
            if (z > zmax) { zmax = z; eid = e; }
            if (lg[e] > lmax) lmax = lg[e];
        }
        float p[8], s = 0.f;
        #pragma unroll
        for (int e = 0; e < 8; e++) { p[e] = expf(lg[e] - lmax); s += p[e]; }
        float inv = 1.0f / s;
        #pragma unroll
        for (int e = 0; e < 8; e++) g_probs[(size_t)gwarp * 8 + e] = p[e] * inv;
        g_expert[gwarp] = eid;
        atomicAdd(&g_counts[eid], 1);
    }
}

// ---------------- kernel 2: offsets scan + aux loss + tile map ----------------
__global__ void scan_aux_kernel(float* __restrict__ out, int out_size) {
    int tid  = threadIdx.x, warp = tid >> 5, lane = tid & 31;
    __shared__ float s_imp[8];
    float s = 0.f;
    for (int t = lane; t < T_TOK; t += 32) s += g_probs[(size_t)t * 8 + warp];
    #pragma unroll
    for (int o = 16; o > 0; o >>= 1) s += __shfl_xor_sync(0xffffffffu, s, o);
    if (lane == 0) s_imp[warp] = s;
    __syncthreads();
    if (tid == 0) {
        int off = 0, n1 = 0;
        #pragma unroll
        for (int e = 0; e < E_EXP; e++) {
            g_offsets[e] = off; g_cursor[e] = off;
            int c = g_counts[e];
            for (int mt = 0; mt * 128 < c; mt++) g_map[n1++] = (e << 8) | mt;
            off += c;
        }
        g_offsets[E_EXP] = off;
        g_ntile = n1;

        float aux = 0.f;
        #pragma unroll
        for (int e = 0; e < E_EXP; e++) {
            float d = s_imp[e] * (1.0f / (float)T_TOK) - (1.0f / (float)E_EXP);
            aux += d * d;
        }
        aux *= (1.0f / (float)E_EXP);
        if (out_size > T_TOK * D_DIM) out[(size_t)T_TOK * D_DIM] = aux;
    }
}

// ---------------- kernel 3: build permutation ----------------
__global__ void perm_kernel() {
    int t = blockIdx.x * blockDim.x + threadIdx.x;
    if (t < T_TOK) {
        int e = g_expert[t];
        int slot = atomicAdd(&g_cursor[e], 1);
        g_perm[slot] = t;
    }
}

// ---------------- grouped fp16 GEMM with in-loop fp32->fp16 weight relay ----------
// CTA 128x256, warp 64x64, KC=32, 3 stages. No weight pre-conversion pass:
// B (weights) is LDG'd as fp32 inside the mainloop, converted RN to fp16 in
// registers, and STS'd. The relay is staggered (half at loop top, half mid-loop)
// to bound live registers at ~16 while keeping >=600-cycle latency windows.
// PHASE 1: hidden = half(gelu(x[perm]@w1+b1))   K=1024, N=4096 (A relay fp32->fp16)
// PHASE 2: out[perm] = hidden@w2+b2 (fp32 out)  K=4096, N=1024 (A via cp.async, fp16)
template <int PHASE>
__global__ __launch_bounds__(256, 1)
void moe_gemm(const float* __restrict__ x, const float* __restrict__ W,
              const float* __restrict__ bias, float* __restrict__ out) {
    constexpr int KTOT = (PHASE == 1) ? D_DIM : H_DIM;
    constexpr int NTOT = (PHASE == 1) ? H_DIM : D_DIM;
    constexpr int MT   = 128;
    constexpr int NT   = 256;
    constexpr int KC   = 32;
    constexpr int NKB  = KTOT / KC;
    constexpr int ABYTES = MT * 64;             // 8192 (64B rows, swizzled)
    constexpr int BROWB  = 528;                 // bytes per B k-row (264 halves)
    constexpr int BBYTES = KC * BROWB;          // 16896
    constexpr int STAGE  = ABYTES + BBYTES;     // 25088

    int nt = blockIdx.x, ms = blockIdx.y;
    if (ms >= g_ntile) return;
    int packed = g_map[ms];
    int e  = packed >> 8, mt = packed & 255;
    int cnt = g_counts[e];
    int mbase = mt * MT;
    int off = g_offsets[e];
    int rv  = min(MT, cnt - mbase);

    extern __shared__ char smraw[];
    char* sm = (char*)(((uintptr_t)smraw + 127) & ~(uintptr_t)127);
    int*  rowtok = (int*)sm;
    char* stg    = sm + 1024;
    uint32_t stg_u = smem_u32(stg);

    int tid = threadIdx.x, lane = tid & 31, wid = tid >> 5;
    if (tid < MT) rowtok[tid] = g_perm[off + mbase + min(tid, rv - 1)];
    __syncthreads();

    // ---- A staging map: chunk (m, kq): m = tid>>2 (+64j), kq = tid&3 ----
    int am = tid >> 2, akq = tid & 3;
    uint32_t aoff[2];
    const float*  axG[2];
    const __half* ahG[2];
    #pragma unroll
    for (int j = 0; j < 2; j++) {
        int m = am + 64 * j;
        aoff[j] = (uint32_t)(m * 64 + (((akq ^ ((m >> 1) & 3))) << 4));
        if (PHASE == 1)
            axG[j] = x + (size_t)rowtok[m] * KTOT + akq * 8;
        else
            ahG[j] = g_hidden + (size_t)(off + mbase + min(m, rv - 1)) * KTOT + akq * 8;
    }
    // ---- B staging map (fp32 source): row k = tid>>3, col group bq = tid&7 ----
    int bk = tid >> 3, bq = tid & 7;
    const float* Wf = W + (size_t)e * KTOT * NTOT + (size_t)bk * NTOT
                        + (size_t)nt * NT + bq * 8;
    uint32_t boff = (uint32_t)(ABYTES + bk * BROWB + bq * 16);

    uint4  apre[2];      // PHASE 1: pre-converted A halves
    float4 b0r[4], b1r[4];   // staggered fp32 B relay (groups j=0..1 and j=2..3)

    auto loadA = [&](int c) {
        int k0 = c * KC;
        #pragma unroll
        for (int j = 0; j < 2; j++) {
            float4 u = *reinterpret_cast<const float4*>(axG[j] + k0);
            float4 v = *reinterpret_cast<const float4*>(axG[j] + k0 + 4);
            apre[j].x = packh2(u.x, u.y); apre[j].y = packh2(u.z, u.w);
            apre[j].z = packh2(v.x, v.y); apre[j].w = packh2(v.z, v.w);
        }
    };
    auto stsA = [&](int s) {
        uint32_t sb = (uint32_t)(s * STAGE);
        #pragma unroll
        for (int j = 0; j < 2; j++)
            *reinterpret_cast<uint4*>(stg + sb + aoff[j]) = apre[j];
    };
    auto loadB0 = [&](int c) {
        int k0 = c * KC;
        #pragma unroll
        for (int j = 0; j < 2; j++) {
            b0r[2*j]   = *reinterpret_cast<const float4*>(Wf + (size_t)k0 * NTOT + j * 64);
            b0r[2*j+1] = *reinterpret_cast<const float4*>(Wf + (size_t)k0 * NTOT + j * 64 + 4);
        }
    };
    auto loadB1 = [&](int c) {
        int k0 = c * KC;
        #pragma unroll
        for (int j = 0; j < 2; j++) {
            b1r[2*j]   = *reinterpret_cast<const float4*>(Wf + (size_t)k0 * NTOT + (j+2) * 64);
            b1r[2*j+1] = *reinterpret_cast<const float4*>(Wf + (size_t)k0 * NTOT + (j+2) * 64 + 4);
        }
    };
    auto stsB = [&](int s, const float4* br, int jbase) {
        uint32_t sb = (uint32_t)(s * STAGE);
        #pragma unroll
        for (int jj = 0; jj < 2; jj++) {
            uint4 o;
            o.x = packh2(br[2*jj].x,   br[2*jj].y);
            o.y = packh2(br[2*jj].z,   br[2*jj].w);
            o.z = packh2(br[2*jj+1].x, br[2*jj+1].y);
            o.w = packh2(br[2*jj+1].z, br[2*jj+1].w);
            *reinterpret_cast<uint4*>(stg + sb + boff + (uint32_t)((jbase + jj) * 128)) = o;
        }
    };

    int g  = lane >> 2, tg = lane & 3;
    int wm = wid & 1,  wn = wid >> 1;          // warp tile 64(m) x 64(n)

    float acc[4][8][4] = {};

    // ---- prologue: stage chunks 0 and 1 ----
    #pragma unroll
    for (int c = 0; c < 2; c++) {
        if (PHASE == 1) loadA(c);
        loadB0(c); loadB1(c);
        if (PHASE == 1) stsA(c);
        else {
            int k0 = c * KC;
            #pragma unroll
            for (int j = 0; j < 2; j++)
                cp_async16(stg_u + (uint32_t)(c * STAGE) + aoff[j], ahG[j] + k0);
        }
        stsB(c, b0r, 0); stsB(c, b1r, 2);
        cp_commit();
    }

    for (int c = 0; c < NKB; c++) {
        bool pre = (c + 2 < NKB);
        if (pre) { if (PHASE == 1) loadA(c + 2); loadB0(c + 2); }
        cp_wait<1>();
        __syncthreads();
        int s  = c % 3;
        int sn = (c + 2) % 3;
        const char*   Ab = stg + s * STAGE;
        const __half* Bh = (const __half*)(stg + s * STAGE + ABYTES);
        #pragma unroll
        for (int ks = 0; ks < 2; ks++) {
            uint32_t af[4][4], bf[8][2];
            #pragma unroll
            for (int mi = 0; mi < 4; mi++) {
                int r0 = wm * 64 + mi * 16 + g;
                af[mi][0] = *reinterpret_cast<const uint32_t*>(Ab + awb(r0,     ks * 8 + tg));
                af[mi][1] = *reinterpret_cast<const uint32_t*>(Ab + awb(r0 + 8, ks * 8 + tg));
                af[mi][2] = *reinterpret_cast<const uint32_t*>(Ab + awb(r0,     ks * 8 + tg + 4));
                af[mi][3] = *reinterpret_cast<const uint32_t*>(Ab + awb(r0 + 8, ks * 8 + tg + 4));
            }
            int kb = ks * 16 + 2 * tg;
            #pragma unroll
            for (int ni = 0; ni < 8; ni++) {
                int n0 = wn * 64 + ni * 8 + g;
                const __half* col = Bh + n0;
                uint32_t h0 = *reinterpret_cast<const uint16_t*>(col + (size_t)(kb    ) * 264);
                uint32_t h1 = *reinterpret_cast<const uint16_t*>(col + (size_t)(kb + 1) * 264);
                bf[ni][0] = h0 | (h1 << 16);
                uint32_t h2 = *reinterpret_cast<const uint16_t*>(col + (size_t)(kb + 8) * 264);
                uint32_t h3 = *reinterpret_cast<const uint16_t*>(col + (size_t)(kb + 9) * 264);
                bf[ni][1] = h2 | (h3 << 16);
            }
            #pragma unroll
            for (int mi = 0; mi < 4; mi++)
                #pragma unroll
                for (int ni = 0; ni < 8; ni++)
                    mma_f16(acc[mi][ni], af[mi], bf[ni]);
            // mid-loop: retire B group0, launch B group1 (staggers live registers)
            if (ks == 0 && pre) { stsB(sn, b0r, 0); loadB1(c + 2); }
        }
        if (pre) {
            stsB(sn, b1r, 2);
            if (PHASE == 1) stsA(sn);
            else {
                int k0 = (c + 2) * KC;
                #pragma unroll
                for (int j = 0; j < 2; j++)
                    cp_async16(stg_u + (uint32_t)(sn * STAGE) + aoff[j], ahG[j] + k0);
            }
        }
        cp_commit();     // keep group accounting aligned every iteration
    }

    // ---- epilogue ----
    #pragma unroll
    for (int mi = 0; mi < 4; mi++) {
        #pragma unroll
        for (int h = 0; h < 2; h++) {
            int r = wm * 64 + mi * 16 + g + h * 8;
            if (r >= rv) continue;
            size_t orow = (PHASE == 1)
                ? (size_t)(off + mbase + r) * H_DIM + (size_t)nt * NT
                : (size_t)rowtok[r] * D_DIM + (size_t)nt * NT;
            #pragma unroll
            for (int ni = 0; ni < 8; ni++) {
                int cl = wn * 64 + ni * 8 + tg * 2;
                float b0 = bias[(size_t)e * NTOT + nt * NT + cl];
                float b1 = bias[(size_t)e * NTOT + nt * NT + cl + 1];
                float v0 = acc[mi][ni][h * 2 + 0] + b0;
                float v1 = acc[mi][ni][h * 2 + 1] + b1;
                if (PHASE == 1) {
                    *reinterpret_cast<__half2*>(g_hidden + orow + cl) =
                        __floats2half2_rn(gelu_exact(v0), gelu_exact(v1));
                } else {
                    out[orow + cl]     = v0;
                    out[orow + cl + 1] = v1;
                }
            }
        }
    }
}

// ---------------- host entry ----------------
extern "C" void kernel_launch(void* const* d_in, const int* in_sizes, int n_in,
                              void* d_out, int out_size) {
    const float* x   = (const float*)d_in[0];   // (4,1024,1024)
    const float* gum = (const float*)d_in[1];   // (4096,8)
    const float* rw  = (const float*)d_in[2];   // (1024,8)
    const float* rb  = (const float*)d_in[3];   // (8,)
    const float* w1  = (const float*)d_in[4];   // (8,1024,4096)
    const float* b1  = (const float*)d_in[5];   // (8,4096)
    const float* w2  = (const float*)d_in[6];   // (8,4096,1024)
    const float* b2  = (const float*)d_in[7];   // (8,1024)
    float* out = (float*)d_out;

    constexpr int SMEM = 1024 + 3 * 25088 + 128;   // 76416
    cudaFuncSetAttribute((const void*)moe_gemm<1>,
                         cudaFuncAttributeMaxDynamicSharedMemorySize, SMEM);
    cudaFuncSetAttribute((const void*)moe_gemm<2>,
                         cudaFuncAttributeMaxDynamicSharedMemorySize, SMEM);

    init_kernel<<<1, 32>>>();
    router_kernel<<<512, 256>>>(x, gum, rw, rb);
    scan_aux_kernel<<<1, 256>>>(out, out_size);
    perm_kernel<<<16, 256>>>();
    // GEMM1: 16 n-tiles of 256 x up to 40 (expert,m)-tiles of M=128; W read fp32 in-loop
    moe_gemm<1><<<dim3(16, 40), 256, SMEM>>>(x, w1, b1, out);
    // GEMM2: 4 n-tiles of 256 (A = g_hidden fp16 via cp.async; W = w2 fp32 in-loop)
    moe_gemm<2><<<dim3(4, 40), 256, SMEM>>>(x, w2, b2, out);
}

// round 17
// speedup vs baseline: 1.2397x; 1.2397x over previous
#include <cuda_runtime.h>
#include <cuda_fp16.h>
#include <cstdint>

// Problem dims
#define T_TOK 4096
#define D_DIM 1024
#define E_EXP 8
#define H_DIM 4096

// ---------------- device scratch (no allocations allowed) ----------------
__device__ int    g_expert[T_TOK];
__device__ int    g_counts[E_EXP];
__device__ int    g_offsets[E_EXP + 1];
__device__ int    g_cursor[E_EXP];
__device__ int    g_perm[T_TOK];
__device__ float  g_probs[T_TOK * E_EXP];
__device__ __half g_hidden[(size_t)T_TOK * H_DIM];            // 32 MB
__device__ int    g_map[48];    // tile list: (e<<8)|mt, M-tile=128
__device__ int    g_ntile;

// ---------------- helpers ----------------
__device__ __forceinline__ float gelu_exact(float v) {
    return 0.5f * v * (1.0f + erff(v * 0.70710678118654752440f));
}
__device__ __forceinline__ uint32_t smem_u32(const void* p) {
    uint32_t a;
    asm("{ .reg .u64 t; cvta.to.shared.u64 t, %1; cvt.u32.u64 %0, t; }" : "=r"(a) : "l"(p));
    return a;
}
__device__ __forceinline__ uint32_t packh2(float a, float b) {
    __half2 h = __floats2half2_rn(a, b);
    return *reinterpret_cast<uint32_t*>(&h);
}
__device__ __forceinline__ void mma_f16(float* c, const uint32_t* a, const uint32_t* b) {
    asm volatile(
        "mma.sync.aligned.m16n8k16.row.col.f32.f16.f16.f32 "
        "{%0,%1,%2,%3}, {%4,%5,%6,%7}, {%8,%9}, {%0,%1,%2,%3};"
        : "+f"(c[0]), "+f"(c[1]), "+f"(c[2]), "+f"(c[3])
        : "r"(a[0]), "r"(a[1]), "r"(a[2]), "r"(a[3]), "r"(b[0]), "r"(b[1]));
}
__device__ __forceinline__ void cp_async16(uint32_t saddr, const void* gptr) {
    asm volatile("cp.async.cg.shared.global [%0], [%1], 16;" :: "r"(saddr), "l"(gptr));
}
__device__ __forceinline__ void cp_commit() {
    asm volatile("cp.async.commit_group;" ::: "memory");
}
template <int N>
__device__ __forceinline__ void cp_wait() {
    asm volatile("cp.async.wait_group %0;" :: "n"(N) : "memory");
}
// A-tile swizzled byte offset: row m (64B rows), half-pair word wk in 0..15
__device__ __forceinline__ uint32_t awb(int m, int wk) {
    return (uint32_t)(m * 64 + (((wk >> 2) ^ ((m >> 1) & 3)) << 4) + (wk & 3) * 4);
}

// ---------------- kernel 0: zero counters ----------------
__global__ void init_kernel() {
    if (threadIdx.x < E_EXP) g_counts[threadIdx.x] = 0;
}

// ---------------- kernel 1: router (one warp per token) ----------------
__global__ void router_kernel(const float* __restrict__ x,
                              const float* __restrict__ gum,
                              const float* __restrict__ rw,
                              const float* __restrict__ rb) {
    int gwarp = (blockIdx.x * blockDim.x + threadIdx.x) >> 5;
    int lane  = threadIdx.x & 31;
    if (gwarp >= T_TOK) return;

    const float* xr = x + (size_t)gwarp * D_DIM;
    float acc[8] = {0.f,0.f,0.f,0.f,0.f,0.f,0.f,0.f};
    for (int d = lane; d < D_DIM; d += 32) {
        float xv = xr[d];
        float4 wa = *reinterpret_cast<const float4*>(rw + (size_t)d * 8);
        float4 wb = *reinterpret_cast<const float4*>(rw + (size_t)d * 8 + 4);
        acc[0] += xv * wa.x; acc[1] += xv * wa.y; acc[2] += xv * wa.z; acc[3] += xv * wa.w;
        acc[4] += xv * wb.x; acc[5] += xv * wb.y; acc[6] += xv * wb.z; acc[7] += xv * wb.w;
    }
    #pragma unroll
    for (int o = 16; o > 0; o >>= 1)
        #pragma unroll
        for (int e = 0; e < 8; e++)
            acc[e] += __shfl_xor_sync(0xffffffffu, acc[e], o);

    if (lane == 0) {
        float lg[8];
        #pragma unroll
        for (int e = 0; e < 8; e++) lg[e] = acc[e] + rb[e];
        float zmax = -1e30f; int eid = 0; float lmax = -1e30f;
        #pragma unroll
        for (int e = 0; e < 8; e++) {
            float z = lg[e] + gum[(size_t)gwarp * 8 + e];
            if (z > zmax) { zmax = z; eid = e; }
            if (lg[e] > lmax) lmax = lg[e];
        }
        float p[8], s = 0.f;
        #pragma unroll
        for (int e = 0; e < 8; e++) { p[e] = expf(lg[e] - lmax); s += p[e]; }
        float inv = 1.0f / s;
        #pragma unroll
        for (int e = 0; e < 8; e++) g_probs[(size_t)gwarp * 8 + e] = p[e] * inv;
        g_expert[gwarp] = eid;
        atomicAdd(&g_counts[eid], 1);
    }
}

// ---------------- kernel 2: offsets scan + aux loss + tile map ----------------
__global__ void scan_aux_kernel(float* __restrict__ out, int out_size) {
    int tid  = threadIdx.x, warp = tid >> 5, lane = tid & 31;
    __shared__ float s_imp[8];
    float s = 0.f;
    for (int t = lane; t < T_TOK; t += 32) s += g_probs[(size_t)t * 8 + warp];
    #pragma unroll
    for (int o = 16; o > 0; o >>= 1) s += __shfl_xor_sync(0xffffffffu, s, o);
    if (lane == 0) s_imp[warp] = s;
    __syncthreads();
    if (tid == 0) {
        int off = 0, n1 = 0;
        #pragma unroll
        for (int e = 0; e < E_EXP; e++) {
            g_offsets[e] = off; g_cursor[e] = off;
            int c = g_counts[e];
            for (int mt = 0; mt * 128 < c; mt++) g_map[n1++] = (e << 8) | mt;
            off += c;
        }
        g_offsets[E_EXP] = off;
        g_ntile = n1;

        float aux = 0.f;
        #pragma unroll
        for (int e = 0; e < E_EXP; e++) {
            float d = s_imp[e] * (1.0f / (float)T_TOK) - (1.0f / (float)E_EXP);
            aux += d * d;
        }
        aux *= (1.0f / (float)E_EXP);
        if (out_size > T_TOK * D_DIM) out[(size_t)T_TOK * D_DIM] = aux;
    }
}

// ---------------- kernel 3: build permutation ----------------
__global__ void perm_kernel() {
    int t = blockIdx.x * blockDim.x + threadIdx.x;
    if (t < T_TOK) {
        int e = g_expert[t];
        int slot = atomicAdd(&g_cursor[e], 1);
        g_perm[slot] = t;
    }
}

// ---------------- grouped GEMM: fp32 B in SMEM, fp16 convert at fragment build ----
// CTA 128x256, warp 64x64, KC=32, 3 stages. NO weight conversion pass:
// B (weights) staged fp32 via cp.async (no relay registers); fp32->fp16 RN pack
// happens when building bf fragments (2xLDS.32 + 1xF2FP = fewer instrs than the
// fp16 path's 2xLDS.u16 + shift + or). Numerically identical to pre-converting.
// B row pad: BROW=260 words -> banks (4*kb + n0) mod 32 cover all 32 exactly once.
// PHASE 1: hidden = half(gelu(x[perm]@w1+b1))   K=1024, N=4096 (A relay fp32->fp16)
// PHASE 2: out[perm] = hidden@w2+b2 (fp32 out)  K=4096, N=1024 (A via cp.async fp16)
template <int PHASE>
__global__ __launch_bounds__(256, 1)
void moe_gemm(const float* __restrict__ x, const float* __restrict__ W,
              const float* __restrict__ bias, float* __restrict__ out) {
    constexpr int KTOT = (PHASE == 1) ? D_DIM : H_DIM;
    constexpr int NTOT = (PHASE == 1) ? H_DIM : D_DIM;
    constexpr int MT   = 128;
    constexpr int NT   = 256;
    constexpr int KC   = 32;
    constexpr int NKB  = KTOT / KC;
    constexpr int ABYTES = MT * 64;             // 8192 (64B rows, swizzled fp16)
    constexpr int BROW   = 260;                 // fp32 words per B k-row (256 + 4 pad)
    constexpr int BROWB  = BROW * 4;            // 1040 bytes
    constexpr int BBYTES = KC * BROWB;          // 33280
    constexpr int STAGE  = ABYTES + BBYTES;     // 41472

    int nt = blockIdx.x, ms = blockIdx.y;
    if (ms >= g_ntile) return;
    int packed = g_map[ms];
    int e  = packed >> 8, mt = packed & 255;
    int cnt = g_counts[e];
    int mbase = mt * MT;
    int off = g_offsets[e];
    int rv  = min(MT, cnt - mbase);

    extern __shared__ char smraw[];
    char* sm = (char*)(((uintptr_t)smraw + 127) & ~(uintptr_t)127);
    int*  rowtok = (int*)sm;
    char* stg    = sm + 1024;
    uint32_t stg_u = smem_u32(stg);

    int tid = threadIdx.x, lane = tid & 31, wid = tid >> 5;
    if (tid < MT) rowtok[tid] = g_perm[off + mbase + min(tid, rv - 1)];
    __syncthreads();

    // ---- A staging map: chunk (m, kq): m = tid>>2 (+64j), kq = tid&3 ----
    int am = tid >> 2, akq = tid & 3;
    uint32_t aoff[2];
    const float*  axG[2];
    const __half* ahG[2];
    #pragma unroll
    for (int j = 0; j < 2; j++) {
        int m = am + 64 * j;
        aoff[j] = (uint32_t)(m * 64 + (((akq ^ ((m >> 1) & 3))) << 4));
        if (PHASE == 1)
            axG[j] = x + (size_t)rowtok[m] * KTOT + akq * 8;
        else
            ahG[j] = g_hidden + (size_t)(off + mbase + min(m, rv - 1)) * KTOT + akq * 8;
    }
    // ---- B staging map (fp32): row k = tid>>3, 8 x 16B at cols (tid&7)*4 + j*32 ----
    int bk = tid >> 3, bq = tid & 7;
    const float* Wf = W + (size_t)e * KTOT * NTOT + (size_t)bk * NTOT
                        + (size_t)nt * NT + bq * 4;
    uint32_t boff = (uint32_t)(ABYTES + bk * BROWB + bq * 16);

    uint4 apre[2];   // PHASE 1: pre-converted A halves for the next staged chunk
    auto loadA = [&](int c) {
        int k0 = c * KC;
        #pragma unroll
        for (int j = 0; j < 2; j++) {
            float4 u = *reinterpret_cast<const float4*>(axG[j] + k0);
            float4 v = *reinterpret_cast<const float4*>(axG[j] + k0 + 4);
            apre[j].x = packh2(u.x, u.y); apre[j].y = packh2(u.z, u.w);
            apre[j].z = packh2(v.x, v.y); apre[j].w = packh2(v.z, v.w);
        }
    };
    auto stage = [&](int c, int s) {
        uint32_t sb = (uint32_t)(s * STAGE);
        int k0 = c * KC;
        if (PHASE == 1) {
            #pragma unroll
            for (int j = 0; j < 2; j++)
                *reinterpret_cast<uint4*>(stg + sb + aoff[j]) = apre[j];
        } else {
            #pragma unroll
            for (int j = 0; j < 2; j++)
                cp_async16(stg_u + sb + aoff[j], ahG[j] + k0);
        }
        #pragma unroll
        for (int j = 0; j < 8; j++)
            cp_async16(stg_u + sb + boff + (uint32_t)(j * 128),
                       Wf + (size_t)k0 * NTOT + j * 32);
        cp_commit();
    };

    int g  = lane >> 2, tg = lane & 3;
    int wm = wid & 1,  wn = wid >> 1;          // warp tile 64(m) x 64(n)

    float acc[4][8][4] = {};

    if (PHASE == 1) { loadA(0); }
    stage(0, 0);
    if (PHASE == 1) { loadA(1); }
    stage(1, 1);

    for (int c = 0; c < NKB; c++) {
        if (PHASE == 1 && c + 2 < NKB) loadA(c + 2);
        cp_wait<1>();
        __syncthreads();
        int s = c % 3;
        const char*  Ab = stg + s * STAGE;
        const float* Bf = (const float*)(stg + s * STAGE + ABYTES);
        #pragma unroll
        for (int ks = 0; ks < 2; ks++) {
            uint32_t af[4][4], bf[8][2];
            #pragma unroll
            for (int mi = 0; mi < 4; mi++) {
                int r0 = wm * 64 + mi * 16 + g;
                af[mi][0] = *reinterpret_cast<const uint32_t*>(Ab + awb(r0,     ks * 8 + tg));
                af[mi][1] = *reinterpret_cast<const uint32_t*>(Ab + awb(r0 + 8, ks * 8 + tg));
                af[mi][2] = *reinterpret_cast<const uint32_t*>(Ab + awb(r0,     ks * 8 + tg + 4));
                af[mi][3] = *reinterpret_cast<const uint32_t*>(Ab + awb(r0 + 8, ks * 8 + tg + 4));
            }
            int kb = ks * 16 + 2 * tg;
            #pragma unroll
            for (int ni = 0; ni < 8; ni++) {
                int n0 = wn * 64 + ni * 8 + g;
                const float* col = Bf + n0;
                bf[ni][0] = packh2(col[(size_t)(kb    ) * BROW],
                                   col[(size_t)(kb + 1) * BROW]);
                bf[ni][1] = packh2(col[(size_t)(kb + 8) * BROW],
                                   col[(size_t)(kb + 9) * BROW]);
            }
            #pragma unroll
            for (int mi = 0; mi < 4; mi++)
                #pragma unroll
                for (int ni = 0; ni < 8; ni++)
                    mma_f16(acc[mi][ni], af[mi], bf[ni]);
        }
        if (c + 2 < NKB) stage(c + 2, (c + 2) % 3);
        else             cp_commit();          // keep group count aligned
    }

    // ---- epilogue ----
    #pragma unroll
    for (int mi = 0; mi < 4; mi++) {
        #pragma unroll
        for (int h = 0; h < 2; h++) {
            int r = wm * 64 + mi * 16 + g + h * 8;
            if (r >= rv) continue;
            size_t orow = (PHASE == 1)
                ? (size_t)(off + mbase + r) * H_DIM + (size_t)nt * NT
                : (size_t)rowtok[r] * D_DIM + (size_t)nt * NT;
            #pragma unroll
            for (int ni = 0; ni < 8; ni++) {
                int cl = wn * 64 + ni * 8 + tg * 2;
                float b0 = bias[(size_t)e * NTOT + nt * NT + cl];
                float b1 = bias[(size_t)e * NTOT + nt * NT + cl + 1];
                float v0 = acc[mi][ni][h * 2 + 0] + b0;
                float v1 = acc[mi][ni][h * 2 + 1] + b1;
                if (PHASE == 1) {
                    *reinterpret_cast<__half2*>(g_hidden + orow + cl) =
                        __floats2half2_rn(gelu_exact(v0), gelu_exact(v1));
                } else {
                    out[orow + cl]     = v0;
                    out[orow + cl + 1] = v1;
                }
            }
        }
    }
}

// ---------------- host entry ----------------
extern "C" void kernel_launch(void* const* d_in, const int* in_sizes, int n_in,
                              void* d_out, int out_size) {
    const float* x   = (const float*)d_in[0];   // (4,1024,1024)
    const float* gum = (const float*)d_in[1];   // (4096,8)
    const float* rw  = (const float*)d_in[2];   // (1024,8)
    const float* rb  = (const float*)d_in[3];   // (8,)
    const float* w1  = (const float*)d_in[4];   // (8,1024,4096)
    const float* b1  = (const float*)d_in[5];   // (8,4096)
    const float* w2  = (const float*)d_in[6];   // (8,4096,1024)
    const float* b2  = (const float*)d_in[7];   // (8,1024)
    float* out = (float*)d_out;

    constexpr int SMEM = 1024 + 3 * 41472 + 128;   // 125568
    cudaFuncSetAttribute((const void*)moe_gemm<1>,
                         cudaFuncAttributeMaxDynamicSharedMemorySize, SMEM);
    cudaFuncSetAttribute((const void*)moe_gemm<2>,
                         cudaFuncAttributeMaxDynamicSharedMemorySize, SMEM);

    init_kernel<<<1, 32>>>();
    router_kernel<<<512, 256>>>(x, gum, rw, rb);
    scan_aux_kernel<<<1, 256>>>(out, out_size);
    perm_kernel<<<16, 256>>>();
    // GEMM1: 16 n-tiles of 256 x up to 40 (expert,m)-tiles of M=128; W fp32 via cp.async
    moe_gemm<1><<<dim3(16, 40), 256, SMEM>>>(x, w1, b1, out);
    // GEMM2: 4 n-tiles of 256 (A = g_hidden fp16; W = w2 fp32 via cp.async)
    moe_gemm<2><<<dim3(4, 40), 256, SMEM>>>(x, w2, b2, out);
}